// round 10
// baseline (speedup 1.0000x reference)
#include <cuda_runtime.h>

// S4D kernel: K[h,l] = 2 * Re( sum_n Cmod[h,n] * exp(dtA[h,n] * l) ),
// H=1024, N=64, L=2048.
//
// Modes merged in pairs: s_k = r_k[n] + r_k[n+1] obeys an ORDER-4 real
// recurrence s_{k+4} = c3 s_{k+3} + c2 s_{k+2} + c1 s_{k+1} + c0 s_k
// (char poly = product of the two mode quadratics; all |roots|<1).
//
// One block (128 thr, 4 warps) per h; lane owns l = lane + 32k, 64 k.
// Warp w owns n in [16w,16w+16) = 4 packed f32x2 stream-pairs per thread.
// Coefficients are warp-uniform: C0,C1 stream from SHARED (broadcast
// LDS.128 per sp per k) instead of registers -> regs drop 80 -> ~64 ->
// 8 blocks/SM -> ALL 1024 blocks resident in a single wave (no tail).
// C2,C3 stay in registers. Init uses fast intrinsics (errors enter
// linearly); per-n coefficient precompute stays precise.

#define N_      64
#define WARPS   4
#define SP      4              // packed stream-pairs per thread
#define CHUNK_K 16             // k-steps per chunk
#define CHUNKS  4

typedef unsigned long long u64;

__device__ __forceinline__ u64 pack2(float lo, float hi) {
    u64 r; asm("mov.b64 %0, {%1,%2};" : "=l"(r) : "f"(lo), "f"(hi)); return r;
}
__device__ __forceinline__ void unpack2(u64 v, float& lo, float& hi) {
    asm("mov.b64 {%0,%1}, %2;" : "=f"(lo), "=f"(hi) : "l"(v));
}
__device__ __forceinline__ u64 fma2(u64 a, u64 b, u64 c) {
    u64 d; asm("fma.rn.f32x2 %0,%1,%2,%3;" : "=l"(d) : "l"(a), "l"(b), "l"(c)); return d;
}
__device__ __forceinline__ u64 mul2(u64 a, u64 b) {
    u64 d; asm("mul.rn.f32x2 %0,%1,%2;" : "=l"(d) : "l"(a), "l"(b)); return d;
}
__device__ __forceinline__ u64 add2(u64 a, u64 b) {
    u64 d; asm("add.rn.f32x2 %0,%1,%2;" : "=l"(d) : "l"(a), "l"(b)); return d;
}

__global__ __launch_bounds__(128, 8)
void s4d_fused(const float* __restrict__ log_dt,
               const float* __restrict__ C,
               const float* __restrict__ A,
               float* __restrict__ out, int L)
{
    __shared__ float2     s_dta[N_], s_cm[N_], s_w32[N_], s_pq[N_];
    __shared__ float4     s_c4[N_ / 2];              // order-4 coeffs per stream
    __shared__ ulonglong2 s_C01[N_ / 4];             // packed {C0,C1} per sp
    __shared__ ulonglong2 s_C23[N_ / 4];             // packed {C2,C3} per sp
    __shared__ u64        s_part[CHUNK_K][WARPS][32];// packed partials, 16KB

    const int h    = blockIdx.x;
    const int tid  = threadIdx.x;
    const int wid  = tid >> 5;
    const int lane = tid & 31;

    // ---- per-n parameter precompute (threads 0..63, one n each).
    //      PRECISE math: coefficient errors shift roots, amplify ~64x. ----
    if (tid < N_) {
        int n = tid;
        float dt  = expf(log_dt[h]);
        float ar  = A[2 * n], ai = A[2 * n + 1];
        float dre = dt * ar, dim = dt * ai;

        float e1 = expf(dre); float s1, c1; sincosf(dim, &s1, &c1);
        float w1r = e1 * c1, w1i = e1 * s1;

        float inv = 1.0f / (ar * ar + ai * ai);
        float nr = w1r - 1.0f, ni = w1i;
        float qdr = (nr * ar + ni * ai) * inv;
        float qdi = (ni * ar - nr * ai) * inv;

        float cr = C[2 * (h * N_ + n)], ci = C[2 * (h * N_ + n) + 1];
        float cmr = 2.0f * (cr * qdr - ci * qdi);
        float cmi = 2.0f * (cr * qdi + ci * qdr);

        float e32 = expf(32.0f * dre); float s32, c32; sincosf(32.0f * dim, &s32, &c32);
        float wr = e32 * c32, wi = e32 * s32;

        s_dta[n] = make_float2(dre, dim);
        s_cm [n] = make_float2(cmr, cmi);
        s_w32[n] = make_float2(wr, wi);
        s_pq [n] = make_float2(2.0f * wr, -(wr * wr + wi * wi));
    }
    __syncthreads();

    // ---- order-4 coeffs per stream: (x^2 - p1 x - q1)(x^2 - p2 x - q2) ----
    if (tid < N_ / 2) {
        float2 a = s_pq[2 * tid], b = s_pq[2 * tid + 1];
        s_c4[tid] = make_float4(-a.y * b.y,                 // c0
                                -(a.x * b.y + b.x * a.y),   // c1
                                a.y + b.y - a.x * b.x,      // c2
                                a.x + b.x);                 // c3
    }
    __syncthreads();

    // ---- pack per-sp coefficient u64s into shared (threads 0..15) ----
    if (tid < N_ / 4) {
        float4 ca = s_c4[2 * tid];
        float4 cb = s_c4[2 * tid + 1];
        ulonglong2 v01, v23;
        v01.x = pack2(ca.x, cb.x);   // C0
        v01.y = pack2(ca.y, cb.y);   // C1
        v23.x = pack2(ca.z, cb.z);   // C2
        v23.y = pack2(ca.w, cb.w);   // C3
        s_C01[tid] = v01;
        s_C23[tid] = v23;
    }
    __syncthreads();

    // ---- per-thread state init (fast intrinsics: errors enter linearly) ----
    const float lf = (float)lane;
    const int   n0 = wid * 16;
    const int   spb = wid * SP;       // first sp index for this warp

    u64 S0[SP], S1[SP], S2[SP], S3[SP];
    u64 C2r[SP], C3r[SP];

#pragma unroll
    for (int j = 0; j < SP; j++) {
        float sm[2][4];
#pragma unroll
        for (int t = 0; t < 2; t++) {
            int ns = n0 + 2 * (2 * j + t);
            float acc[4] = {0.f, 0.f, 0.f, 0.f};
#pragma unroll
            for (int u = 0; u < 2; u++) {
                int n = ns + u;
                float2 d = s_dta[n];
                float ex = __expf(d.x * lf);
                float s, c; __sincosf(d.y * lf, &s, &c);
                float er = ex * c, ei = ex * s;
                float2 cm = s_cm[n];
                float zr = cm.x * er - cm.y * ei;
                float zi = cm.x * ei + cm.y * er;
                float2 w = s_w32[n];
#pragma unroll
                for (int k = 0; k < 4; k++) {
                    acc[k] += zr;
                    float tr = zr * w.x - zi * w.y;
                    float ti = zr * w.y + zi * w.x;
                    zr = tr; zi = ti;
                }
            }
#pragma unroll
            for (int k = 0; k < 4; k++) sm[t][k] = acc[k];
        }
        S0[j] = pack2(sm[0][0], sm[1][0]);
        S1[j] = pack2(sm[0][1], sm[1][1]);
        S2[j] = pack2(sm[0][2], sm[1][2]);
        S3[j] = pack2(sm[0][3], sm[1][3]);

        ulonglong2 v23 = s_C23[spb + j];
        C2r[j] = v23.x;
        C3r[j] = v23.y;
    }

    float* orow  = out + (size_t)h * L;
    u64*   s_slot = &s_part[0][wid][lane];
    const ulonglong2* c01p = &s_C01[spb];

#pragma unroll 1
    for (int ch = 0; ch < CHUNKS; ch++) {
        if (ch) __syncthreads();            // buffer reusable

#pragma unroll 1
        for (int k4 = 0; k4 < CHUNK_K; k4 += 4) {
#pragma unroll
            for (int kk = 0; kk < 4; kk++) {
                u64 a0, a1;
                if (kk == 0) {
                    a0 = add2(S0[0], S0[1]); a1 = add2(S0[2], S0[3]);
#pragma unroll
                    for (int j = 0; j < SP; j++) {
                        ulonglong2 c = c01p[j];    // broadcast LDS.128
                        S0[j] = fma2(C3r[j], S3[j], fma2(C2r[j], S2[j],
                                 fma2(c.y, S1[j], mul2(c.x, S0[j]))));
                    }
                } else if (kk == 1) {
                    a0 = add2(S1[0], S1[1]); a1 = add2(S1[2], S1[3]);
#pragma unroll
                    for (int j = 0; j < SP; j++) {
                        ulonglong2 c = c01p[j];
                        S1[j] = fma2(C3r[j], S0[j], fma2(C2r[j], S3[j],
                                 fma2(c.y, S2[j], mul2(c.x, S1[j]))));
                    }
                } else if (kk == 2) {
                    a0 = add2(S2[0], S2[1]); a1 = add2(S2[2], S2[3]);
#pragma unroll
                    for (int j = 0; j < SP; j++) {
                        ulonglong2 c = c01p[j];
                        S2[j] = fma2(C3r[j], S1[j], fma2(C2r[j], S0[j],
                                 fma2(c.y, S3[j], mul2(c.x, S2[j]))));
                    }
                } else {
                    a0 = add2(S3[0], S3[1]); a1 = add2(S3[2], S3[3]);
#pragma unroll
                    for (int j = 0; j < SP; j++) {
                        ulonglong2 c = c01p[j];
                        S3[j] = fma2(C3r[j], S2[j], fma2(C2r[j], S1[j],
                                 fma2(c.y, S0[j], mul2(c.x, S3[j]))));
                    }
                }
                s_slot[(size_t)(k4 + kk) * (WARPS * 32)] = add2(a0, a1);
            }
        }
        __syncthreads();

        // ---- cross-warp reduction: warp w handles k = w + 4i ----
#pragma unroll
        for (int i = 0; i < CHUNK_K / WARPS; i++) {
            int k = wid + WARPS * i;
            float sum = 0.0f;
#pragma unroll
            for (int w = 0; w < WARPS; w++) {
                float lo, hi;
                unpack2(s_part[k][w][lane], lo, hi);
                sum += lo + hi;
            }
            orow[(size_t)(ch * CHUNK_K + k) * 32 + lane] = sum;
        }
    }
}

extern "C" void kernel_launch(void* const* d_in, const int* in_sizes, int n_in,
                              void* d_out, int out_size)
{
    const float* log_dt = (const float*)d_in[0];
    const float* C      = (const float*)d_in[1];
    const float* A      = (const float*)d_in[2];
    // d_in[3] = input_length scalar; L derived from out_size.

    int H = in_sizes[0];          // 1024
    int L = out_size / H;         // 2048

    s4d_fused<<<H, 128>>>(log_dt, C, A, (float*)d_out, L);
}

// round 11
// speedup vs baseline: 1.7193x; 1.7193x over previous
#include <cuda_runtime.h>

// S4D kernel: K[h,l] = 2 * Re( sum_n Cmod[h,n] * exp(dtA[h,n] * l) ),
// H=1024, N=64, L=2048.
//
// Modes merged in pairs: s_k = r_k[n] + r_k[n+1] obeys an ORDER-4 real
// recurrence s_{k+4} = c3 s_{k+3} + c2 s_{k+2} + c1 s_{k+1} + c0 s_k
// (char poly = product of the two mode quadratics; all |roots|<1).
//
// One block (128 thr, 4 warps) per h; lane owns l = lane + 32k, 64 k.
// Warp w owns n in [16w,16w+16) = 4 packed f32x2 stream-pairs per thread.
// C0 (warp-uniform) streams from shared via broadcast LDS.64; C1,C2,C3 in
// registers. Frees exactly 8 regs vs R9 (80 -> 72) so launch_bounds(128,7)
// is met WITHOUT spills -> 7 blocks/SM -> all 1024 blocks in one wave.

#define N_      64
#define WARPS   4
#define SP      4              // packed stream-pairs per thread
#define CHUNK_K 16             // k-steps per chunk
#define CHUNKS  4

typedef unsigned long long u64;

__device__ __forceinline__ u64 pack2(float lo, float hi) {
    u64 r; asm("mov.b64 %0, {%1,%2};" : "=l"(r) : "f"(lo), "f"(hi)); return r;
}
__device__ __forceinline__ void unpack2(u64 v, float& lo, float& hi) {
    asm("mov.b64 {%0,%1}, %2;" : "=f"(lo), "=f"(hi) : "l"(v));
}
__device__ __forceinline__ u64 fma2(u64 a, u64 b, u64 c) {
    u64 d; asm("fma.rn.f32x2 %0,%1,%2,%3;" : "=l"(d) : "l"(a), "l"(b), "l"(c)); return d;
}
__device__ __forceinline__ u64 mul2(u64 a, u64 b) {
    u64 d; asm("mul.rn.f32x2 %0,%1,%2;" : "=l"(d) : "l"(a), "l"(b)); return d;
}
__device__ __forceinline__ u64 add2(u64 a, u64 b) {
    u64 d; asm("add.rn.f32x2 %0,%1,%2;" : "=l"(d) : "l"(a), "l"(b)); return d;
}

__global__ __launch_bounds__(128, 7)
void s4d_fused(const float* __restrict__ log_dt,
               const float* __restrict__ C,
               const float* __restrict__ A,
               float* __restrict__ out, int L)
{
    __shared__ float2 s_dta[N_], s_cm[N_], s_w32[N_], s_pq[N_];
    __shared__ float4 s_c4[N_ / 2];                 // order-4 coeffs per stream
    __shared__ u64    s_C0[N_ / 4];                 // packed C0 per stream-pair
    __shared__ u64    s_part[CHUNK_K][WARPS][32];   // packed partials, 16KB

    const int h    = blockIdx.x;
    const int tid  = threadIdx.x;
    const int wid  = tid >> 5;
    const int lane = tid & 31;

    // ---- per-n parameter precompute (threads 0..63, one n each).
    //      PRECISE math: coefficient errors shift roots, amplify ~64x. ----
    if (tid < N_) {
        int n = tid;
        float dt  = expf(log_dt[h]);
        float ar  = A[2 * n], ai = A[2 * n + 1];
        float dre = dt * ar, dim = dt * ai;

        float e1 = expf(dre); float s1, c1; sincosf(dim, &s1, &c1);
        float w1r = e1 * c1, w1i = e1 * s1;

        float inv = 1.0f / (ar * ar + ai * ai);
        float nr = w1r - 1.0f, ni = w1i;
        float qdr = (nr * ar + ni * ai) * inv;
        float qdi = (ni * ar - nr * ai) * inv;

        float cr = C[2 * (h * N_ + n)], ci = C[2 * (h * N_ + n) + 1];
        float cmr = 2.0f * (cr * qdr - ci * qdi);
        float cmi = 2.0f * (cr * qdi + ci * qdr);

        float e32 = expf(32.0f * dre); float s32, c32; sincosf(32.0f * dim, &s32, &c32);
        float wr = e32 * c32, wi = e32 * s32;

        s_dta[n] = make_float2(dre, dim);
        s_cm [n] = make_float2(cmr, cmi);
        s_w32[n] = make_float2(wr, wi);
        s_pq [n] = make_float2(2.0f * wr, -(wr * wr + wi * wi));
    }
    __syncthreads();

    // ---- order-4 coeffs per stream: (x^2 - p1 x - q1)(x^2 - p2 x - q2) ----
    if (tid < N_ / 2) {
        float2 a = s_pq[2 * tid], b = s_pq[2 * tid + 1];
        s_c4[tid] = make_float4(-a.y * b.y,                 // c0
                                -(a.x * b.y + b.x * a.y),   // c1
                                a.y + b.y - a.x * b.x,      // c2
                                a.x + b.x);                 // c3
    }
    __syncthreads();

    // ---- pack per-sp C0 into shared (threads 0..15) ----
    if (tid < N_ / 4) {
        float4 ca = s_c4[2 * tid];
        float4 cb = s_c4[2 * tid + 1];
        s_C0[tid] = pack2(ca.x, cb.x);
    }
    __syncthreads();

    // ---- per-thread state init (fast intrinsics: errors enter linearly) ----
    const float lf = (float)lane;
    const int   n0 = wid * 16;
    const int   spb = wid * SP;       // first sp index for this warp

    u64 S0[SP], S1[SP], S2[SP], S3[SP];
    u64 C1r[SP], C2r[SP], C3r[SP];

#pragma unroll
    for (int j = 0; j < SP; j++) {
        float sm[2][4];
#pragma unroll
        for (int t = 0; t < 2; t++) {
            int ns = n0 + 2 * (2 * j + t);
            float acc[4] = {0.f, 0.f, 0.f, 0.f};
#pragma unroll
            for (int u = 0; u < 2; u++) {
                int n = ns + u;
                float2 d = s_dta[n];
                float ex = __expf(d.x * lf);
                float s, c; __sincosf(d.y * lf, &s, &c);
                float er = ex * c, ei = ex * s;
                float2 cm = s_cm[n];
                float zr = cm.x * er - cm.y * ei;
                float zi = cm.x * ei + cm.y * er;
                float2 w = s_w32[n];
#pragma unroll
                for (int k = 0; k < 4; k++) {
                    acc[k] += zr;
                    float tr = zr * w.x - zi * w.y;
                    float ti = zr * w.y + zi * w.x;
                    zr = tr; zi = ti;
                }
            }
#pragma unroll
            for (int k = 0; k < 4; k++) sm[t][k] = acc[k];
        }
        S0[j] = pack2(sm[0][0], sm[1][0]);
        S1[j] = pack2(sm[0][1], sm[1][1]);
        S2[j] = pack2(sm[0][2], sm[1][2]);
        S3[j] = pack2(sm[0][3], sm[1][3]);

        float4 ca = s_c4[2 * (spb + j)];
        float4 cb = s_c4[2 * (spb + j) + 1];
        C1r[j] = pack2(ca.y, cb.y);
        C2r[j] = pack2(ca.z, cb.z);
        C3r[j] = pack2(ca.w, cb.w);
    }

    float* orow   = out + (size_t)h * L;
    u64*   s_slot = &s_part[0][wid][lane];
    const u64* c0p = &s_C0[spb];

#pragma unroll 1
    for (int ch = 0; ch < CHUNKS; ch++) {
        if (ch) __syncthreads();            // buffer reusable

#pragma unroll 1
        for (int k4 = 0; k4 < CHUNK_K; k4 += 4) {
#pragma unroll
            for (int kk = 0; kk < 4; kk++) {
                u64 a0, a1;
                if (kk == 0) {
                    a0 = add2(S0[0], S0[1]); a1 = add2(S0[2], S0[3]);
#pragma unroll
                    for (int j = 0; j < SP; j++)
                        S0[j] = fma2(C3r[j], S3[j], fma2(C2r[j], S2[j],
                                 fma2(C1r[j], S1[j], mul2(c0p[j], S0[j]))));
                } else if (kk == 1) {
                    a0 = add2(S1[0], S1[1]); a1 = add2(S1[2], S1[3]);
#pragma unroll
                    for (int j = 0; j < SP; j++)
                        S1[j] = fma2(C3r[j], S0[j], fma2(C2r[j], S3[j],
                                 fma2(C1r[j], S2[j], mul2(c0p[j], S1[j]))));
                } else if (kk == 2) {
                    a0 = add2(S2[0], S2[1]); a1 = add2(S2[2], S2[3]);
#pragma unroll
                    for (int j = 0; j < SP; j++)
                        S2[j] = fma2(C3r[j], S1[j], fma2(C2r[j], S0[j],
                                 fma2(C1r[j], S3[j], mul2(c0p[j], S2[j]))));
                } else {
                    a0 = add2(S3[0], S3[1]); a1 = add2(S3[2], S3[3]);
#pragma unroll
                    for (int j = 0; j < SP; j++)
                        S3[j] = fma2(C3r[j], S2[j], fma2(C2r[j], S1[j],
                                 fma2(C1r[j], S0[j], mul2(c0p[j], S3[j]))));
                }
                s_slot[(size_t)(k4 + kk) * (WARPS * 32)] = add2(a0, a1);
            }
        }
        __syncthreads();

        // ---- cross-warp reduction: warp w handles k = w + 4i ----
#pragma unroll
        for (int i = 0; i < CHUNK_K / WARPS; i++) {
            int k = wid + WARPS * i;
            float sum = 0.0f;
#pragma unroll
            for (int w = 0; w < WARPS; w++) {
                float lo, hi;
                unpack2(s_part[k][w][lane], lo, hi);
                sum += lo + hi;
            }
            orow[(size_t)(ch * CHUNK_K + k) * 32 + lane] = sum;
        }
    }
}

extern "C" void kernel_launch(void* const* d_in, const int* in_sizes, int n_in,
                              void* d_out, int out_size)
{
    const float* log_dt = (const float*)d_in[0];
    const float* C      = (const float*)d_in[1];
    const float* A      = (const float*)d_in[2];
    // d_in[3] = input_length scalar; L derived from out_size.

    int H = in_sizes[0];          // 1024
    int L = out_size / H;         // 2048

    s4d_fused<<<H, 128>>>(log_dt, C, A, (float*)d_out, L);
}

// round 13
// speedup vs baseline: 2.9437x; 1.7121x over previous
#include <cuda_runtime.h>
#include <cuda_bf16.h>
#include <cstdint>

// S4D via warp-level tensor cores (mma.sync bf16 — compiles for compute_103;
// tcgen05 does not). K[h, 32m + r] = Re( sum_n V[h,n,m] * U[h,n,r] ),
//   V = w32^m (m=0..63), U = cm*w^r (r=0..31), w = exp(dtA), w32 = w^32.
// Per h: D[64x32] = A[64x128] @ B[128x32],
//   A[m][n]    = Re(w32^m),  A[m][64+n]  = Im(w32^m)
//   B[n][r]    = Re(cm w^r), B[64+n][r]  = -Im(cm w^r)
// bf16 2-way operand split, 3 products (AhBh + AlBh + AhBl), fp32 accum.
// Operands staged into smem via complex-multiply recurrences (no per-element
// transcendentals). ldmatrix x4 feeds mma.sync.m16n8k16.
//
// smem rows padded to 272B: 16B-aligned rows, conflict-free LDSM.

#define RSE   136                    // row stride in bf16 elems (272 B)
#define OFF_CM   0                   // float2[64]
#define OFF_W1   512                 // float2[64]
#define OFF_W16  1024                // float2[64]
#define OFF_W32  1536                // float2[64]
#define OFF_WP   2048                // float2[64]  w32^32
#define OFF_AH   2560                // 64 x 272B = 17408
#define OFF_AL   (OFF_AH + 17408)
#define OFF_BH   (OFF_AL + 17408)    // 32 x 272B = 8704
#define OFF_BL   (OFF_BH + 8704)
#define SMEM_TOTAL (OFF_BL + 8704)   // 54784

typedef uint32_t u32;

__device__ __forceinline__ u32 smem_u32(const void* p) {
    u32 a;
    asm("{ .reg .u64 t; cvta.to.shared.u64 t, %1; cvt.u32.u64 %0, t; }"
        : "=r"(a) : "l"(p));
    return a;
}
__device__ __forceinline__ void ldsm4(u32 r[4], u32 addr) {
    asm volatile("ldmatrix.sync.aligned.m8n8.x4.shared.b16 {%0,%1,%2,%3}, [%4];"
                 : "=r"(r[0]), "=r"(r[1]), "=r"(r[2]), "=r"(r[3]) : "r"(addr));
}
__device__ __forceinline__ void mma_bf16(float d[4], const u32 a[4],
                                         u32 b0, u32 b1) {
    asm volatile(
        "mma.sync.aligned.m16n8k16.row.col.f32.bf16.bf16.f32 "
        "{%0,%1,%2,%3}, {%4,%5,%6,%7}, {%8,%9}, {%0,%1,%2,%3};"
        : "+f"(d[0]), "+f"(d[1]), "+f"(d[2]), "+f"(d[3])
        : "r"(a[0]), "r"(a[1]), "r"(a[2]), "r"(a[3]), "r"(b0), "r"(b1));
}
__device__ __forceinline__ __nv_bfloat16 bfh(float x) {
    return __float2bfloat16_rn(x);
}

extern "C" __global__ void __launch_bounds__(128)
s4d_hmma(const float* __restrict__ log_dt, const float* __restrict__ C,
         const float* __restrict__ A, float* __restrict__ out)
{
    extern __shared__ __align__(256) char sm[];
    const u32 sb  = smem_u32(sm);
    const int tid = threadIdx.x, wid = tid >> 5, lane = tid & 31;
    const int h   = blockIdx.x;

    float2* s_cm  = (float2*)(sm + OFF_CM);
    float2* s_w1  = (float2*)(sm + OFF_W1);
    float2* s_w16 = (float2*)(sm + OFF_W16);
    float2* s_w32 = (float2*)(sm + OFF_W32);
    float2* s_wP  = (float2*)(sm + OFF_WP);
    __nv_bfloat16* AH = (__nv_bfloat16*)(sm + OFF_AH);
    __nv_bfloat16* AL = (__nv_bfloat16*)(sm + OFF_AL);
    __nv_bfloat16* BH = (__nv_bfloat16*)(sm + OFF_BH);
    __nv_bfloat16* BL = (__nv_bfloat16*)(sm + OFF_BL);

    // ---- precise per-n params (threads 0..63) ----
    if (tid < 64) {
        int n = tid;
        float dt  = expf(log_dt[h]);
        float ar  = A[2 * n], ai = A[2 * n + 1];
        float dre = dt * ar, dim = dt * ai;

        float e1 = expf(dre); float s1, c1; sincosf(dim, &s1, &c1);
        float w1r = e1 * c1, w1i = e1 * s1;
        float inv = 1.0f / (ar * ar + ai * ai);
        float nr = w1r - 1.0f, ni = w1i;
        float qdr = (nr * ar + ni * ai) * inv;
        float qdi = (ni * ar - nr * ai) * inv;
        float cr = C[2 * (h * 64 + n)], ci = C[2 * (h * 64 + n) + 1];

        s_cm[n] = make_float2(2.0f * (cr * qdr - ci * qdi),
                              2.0f * (cr * qdi + ci * qdr));
        s_w1[n] = make_float2(w1r, w1i);

        float e, s, c;
        e = expf(16.0f * dre);   sincosf(16.0f * dim, &s, &c);
        s_w16[n] = make_float2(e * c, e * s);
        e = expf(32.0f * dre);   sincosf(32.0f * dim, &s, &c);
        s_w32[n] = make_float2(e * c, e * s);
        e = expf(1024.0f * dre); sincosf(1024.0f * dim, &s, &c);
        s_wP[n] = make_float2(e * c, e * s);
    }
    __syncthreads();

    // ---- stage A (V = w32^m): thread = (n, m-half); recurrence over m ----
    {
        const int n = tid & 63, half = tid >> 6;
        float2 w = s_w32[n];
        float zr, zi;
        if (half) { float2 p = s_wP[n]; zr = p.x; zi = p.y; }
        else      { zr = 1.0f; zi = 0.0f; }
        int m = half * 32;
#pragma unroll 4
        for (int i = 0; i < 32; i++, m++) {
            __nv_bfloat16 rh = bfh(zr), ih = bfh(zi);
            AH[m * RSE + n]      = rh;
            AH[m * RSE + 64 + n] = ih;
            AL[m * RSE + n]      = bfh(zr - __bfloat162float(rh));
            AL[m * RSE + 64 + n] = bfh(zi - __bfloat162float(ih));
            float tr = zr * w.x - zi * w.y;
            float ti = zr * w.y + zi * w.x;
            zr = tr; zi = ti;
        }
    }

    // ---- stage B (U = cm*w^r, Im negated): thread = (n, r-half) ----
    {
        const int n = tid & 63, half = tid >> 6;
        float2 w = s_w1[n];
        float2 cm = s_cm[n];
        float zr = cm.x, zi = cm.y;
        if (half) {
            float2 w16 = s_w16[n];
            float tr = zr * w16.x - zi * w16.y;
            float ti = zr * w16.y + zi * w16.x;
            zr = tr; zi = ti;
        }
        int r = half * 16;
#pragma unroll 4
        for (int i = 0; i < 16; i++, r++) {
            float vim = -zi;
            __nv_bfloat16 rh = bfh(zr), ih = bfh(vim);
            BH[r * RSE + n]      = rh;
            BH[r * RSE + 64 + n] = ih;
            BL[r * RSE + n]      = bfh(zr  - __bfloat162float(rh));
            BL[r * RSE + 64 + n] = bfh(vim - __bfloat162float(ih));
            float tr = zr * w.x - zi * w.y;
            float ti = zr * w.y + zi * w.x;
            zr = tr; zi = ti;
        }
    }
    __syncthreads();

    // NOTE on roles in the GEMM below: A operand rows = m (power index,
    // M=64), stored [m][K=128]; B operand from Bt[r][K] rows = r (N=32).
    // Wait — staging above wrote A as [m][mode] and B as [r][mode]; both are
    // [row][K-dim] row-major, exactly what normal ldmatrix needs for A frags
    // and B frags (B fragment k-pairs are contiguous along K in Bt rows).

    // ---- per-lane ldmatrix base addresses ----
    const int g   = lane >> 3, l8 = lane & 7;
    const int mb  = wid * 16;
    // A x4: regs {a0,a1,a2,a3} = (m,k),(m+8,k),(m,k+8),(m+8,k+8)
    const u32 aRow = (u32)(mb + (g & 1) * 8 + l8);
    const u32 aCol = (u32)((g >> 1) * 16);               // bytes
    const u32 aH = sb + OFF_AH + aRow * 272u + aCol;
    const u32 aL = sb + OFF_AL + aRow * 272u + aCol;
    // B x4 (covers n-tiles 2P,2P+1): regs {b0(nt),b1(nt),b0(nt+1),b1(nt+1)}
    const u32 bRow = (u32)((g >> 1) * 8 + l8);
    const u32 bCol = (u32)((g & 1) * 16);                // bytes
    const u32 bH = sb + OFF_BH + bRow * 272u + bCol;
    const u32 bL = sb + OFF_BL + bRow * 272u + bCol;

    float d0[4] = {0,0,0,0}, d1[4] = {0,0,0,0};
    float d2[4] = {0,0,0,0}, d3[4] = {0,0,0,0};

#pragma unroll
    for (int s = 0; s < 8; s++) {
        const u32 ko = (u32)s * 32u;                     // 16 k * 2B
        u32 ah[4], al[4], bh[4], bl[4];
        ldsm4(ah, aH + ko);
        ldsm4(al, aL + ko);
        // P = 0: n-tiles 0,1
        ldsm4(bh, bH + ko);
        ldsm4(bl, bL + ko);
        mma_bf16(d0, ah, bh[0], bh[1]);
        mma_bf16(d1, ah, bh[2], bh[3]);
        mma_bf16(d0, al, bh[0], bh[1]);
        mma_bf16(d1, al, bh[2], bh[3]);
        mma_bf16(d0, ah, bl[0], bl[1]);
        mma_bf16(d1, ah, bl[2], bl[3]);
        // P = 1: n-tiles 2,3 (rows +16)
        ldsm4(bh, bH + 16u * 272u + ko);
        ldsm4(bl, bL + 16u * 272u + ko);
        mma_bf16(d2, ah, bh[0], bh[1]);
        mma_bf16(d3, ah, bh[2], bh[3]);
        mma_bf16(d2, al, bh[0], bh[1]);
        mma_bf16(d3, al, bh[2], bh[3]);
        mma_bf16(d2, ah, bl[0], bl[1]);
        mma_bf16(d3, ah, bl[2], bl[3]);
    }

    // ---- store D: out[h*2048 + m*32 + r] ----
    {
        const int lr = lane >> 2, lc = lane & 3;
        const int m0 = mb + lr;
        const int r0 = lc * 2;
        float* o = out + (size_t)h * 2048;
        *(float2*)(o + (m0    ) * 32 + r0     ) = make_float2(d0[0], d0[1]);
        *(float2*)(o + (m0 + 8) * 32 + r0     ) = make_float2(d0[2], d0[3]);
        *(float2*)(o + (m0    ) * 32 + r0 +  8) = make_float2(d1[0], d1[1]);
        *(float2*)(o + (m0 + 8) * 32 + r0 +  8) = make_float2(d1[2], d1[3]);
        *(float2*)(o + (m0    ) * 32 + r0 + 16) = make_float2(d2[0], d2[1]);
        *(float2*)(o + (m0 + 8) * 32 + r0 + 16) = make_float2(d2[2], d2[3]);
        *(float2*)(o + (m0    ) * 32 + r0 + 24) = make_float2(d3[0], d3[1]);
        *(float2*)(o + (m0 + 8) * 32 + r0 + 24) = make_float2(d3[2], d3[3]);
    }
}

extern "C" void kernel_launch(void* const* d_in, const int* in_sizes, int n_in,
                              void* d_out, int out_size)
{
    const float* log_dt = (const float*)d_in[0];
    const float* C      = (const float*)d_in[1];
    const float* A      = (const float*)d_in[2];

    int H = in_sizes[0];   // 1024

    static int configured = 0;
    cudaFuncSetAttribute(s4d_hmma, cudaFuncAttributeMaxDynamicSharedMemorySize,
                         SMEM_TOTAL);
    (void)configured;
    s4d_hmma<<<H, 128, SMEM_TOTAL>>>(log_dt, C, A, (float*)d_out);
}